// round 2
// baseline (speedup 1.0000x reference)
#include <cuda_runtime.h>

#define NN 512
#define CC 16
#define LTL 3
#define AGG_IN 1028
#define TPB 256

// ping-pong activation buffers (no allocation allowed)
__device__ float g_act[2][NN];

__device__ __forceinline__ float tanh_e(float x) {
    // accurate fast tanh: (e^2x - 1)/(e^2x + 1), ex2.approx + rcp.approx (~1e-6 rel err)
    x = fminf(fmaxf(x, -15.0f), 15.0f);
    float e = __expf(2.0f * x);
    return __fdividef(e - 1.0f, e + 1.0f);
}

__global__ __launch_bounds__(TPB) void layer_kernel(
    const float* __restrict__ a_ext,   // layer 0 input (x) or nullptr
    float* __restrict__ dout,          // final output (reversed) or nullptr
    int in_buf, int out_buf,           // g_act selectors
    const float* __restrict__ vW,  const float* __restrict__ vb,
    const float* __restrict__ sW1, const float* __restrict__ sb1,
    const float* __restrict__ sW2, const float* __restrict__ sb2,
    const float* __restrict__ aW1, const float* __restrict__ ab1,
    const float* __restrict__ aW2, const float* __restrict__ ab2,
    int l)
{
    const int q = blockIdx.x;
    const int t = threadIdx.x;

    __shared__ float sh_s[NN];
    __shared__ float red[3][TPB / 32];

    const float* a_in = a_ext ? a_ext : g_act[in_buf];

    #pragma unroll
    for (int j = 0; j < NN / TPB; ++j) {
        const int p = t + j * TPB;
        const size_t edge = (size_t)q * NN + p;
        const float ap = __ldg(&a_in[p]);

        // --- VEC: filtered[c] = tanh(a[p]*vW[c] + vb[c]),  c = 0..15 ---
        const float4* vW4 = (const float4*)(vW + edge * CC);
        const float4* vb4 = (const float4*)(vb + edge * CC);
        float f[16];
        #pragma unroll
        for (int cc = 0; cc < 4; ++cc) {
            float4 w = vW4[cc];
            float4 b = vb4[cc];
            f[4*cc+0] = tanh_e(fmaf(ap, w.x, b.x));
            f[4*cc+1] = tanh_e(fmaf(ap, w.y, b.y));
            f[4*cc+2] = tanh_e(fmaf(ap, w.z, b.z));
            f[4*cc+3] = tanh_e(fmaf(ap, w.w, b.w));
        }

        // --- Synapse: Linear(16->3) -> tanh -> Linear(3->1) -> tanh ---
        const float4* W14 = (const float4*)(sW1 + edge * 48);
        float h1[3];
        #pragma unroll
        for (int o = 0; o < 3; ++o) {
            float acc = sb1[edge * 3 + o];
            #pragma unroll
            for (int cc = 0; cc < 4; ++cc) {
                float4 w = W14[o * 4 + cc];
                acc = fmaf(w.x, f[4*cc+0], acc);
                acc = fmaf(w.y, f[4*cc+1], acc);
                acc = fmaf(w.z, f[4*cc+2], acc);
                acc = fmaf(w.w, f[4*cc+3], acc);
            }
            h1[o] = tanh_e(acc);
        }
        float sv = sb2[edge];
        sv = fmaf(sW2[edge * 3 + 0], h1[0], sv);
        sv = fmaf(sW2[edge * 3 + 1], h1[1], sv);
        sv = fmaf(sW2[edge * 3 + 2], h1[2], sv);
        sh_s[p] = tanh_e(sv);
    }
    __syncthreads();

    // --- Aggregator: h_k = tanh(sum_p aW1[q,k,p]*s[p] + lcode + eye + b) ---
    float pk[3] = {0.f, 0.f, 0.f};
    #pragma unroll
    for (int k = 0; k < 3; ++k) {
        const float* row = aW1 + ((size_t)q * 3 + k) * AGG_IN;
        #pragma unroll
        for (int j = 0; j < NN / TPB; ++j) {
            const int p = t + j * TPB;
            pk[k] = fmaf(row[p], sh_s[p], pk[k]);
        }
    }
    #pragma unroll
    for (int off = 16; off > 0; off >>= 1) {
        pk[0] += __shfl_down_sync(0xffffffffu, pk[0], off);
        pk[1] += __shfl_down_sync(0xffffffffu, pk[1], off);
        pk[2] += __shfl_down_sync(0xffffffffu, pk[2], off);
    }
    if ((t & 31) == 0) {
        const int w = t >> 5;
        red[0][w] = pk[0];
        red[1][w] = pk[1];
        red[2][w] = pk[2];
    }
    __syncthreads();

    if (t == 0) {
        float out = ab2[q];
        #pragma unroll
        for (int k = 0; k < 3; ++k) {
            float tot = 0.f;
            #pragma unroll
            for (int w = 0; w < TPB / 32; ++w) tot += red[k][w];
            const float* row = aW1 + ((size_t)q * 3 + k) * AGG_IN;
            // layer one-hot at position N+l+1, node one-hot at N+NLAYERS+q
            tot += row[NN + l + 1] + row[NN + 4 + q] + ab1[q * 3 + k];
            out = fmaf(aW2[q * 3 + k], tanh_e(tot), out);
        }
        if (dout) dout[NN - 1 - q] = out;     // final layer: reversed output
        else      g_act[out_buf][q] = out;
    }
}

extern "C" void kernel_launch(void* const* d_in, const int* in_sizes, int n_in,
                              void* d_out, int out_size)
{
    const float* x      = (const float*)d_in[0];
    const float* vec_W  = (const float*)d_in[1];
    const float* vec_b  = (const float*)d_in[2];
    const float* syn_W1 = (const float*)d_in[3];
    const float* syn_b1 = (const float*)d_in[4];
    const float* syn_W2 = (const float*)d_in[5];
    const float* syn_b2 = (const float*)d_in[6];
    const float* agg_W1 = (const float*)d_in[7];
    const float* agg_b1 = (const float*)d_in[8];
    const float* agg_W2 = (const float*)d_in[9];
    const float* agg_b2 = (const float*)d_in[10];
    float* out = (float*)d_out;

    const size_t VEC_L  = (size_t)NN * NN * CC;   // 4,194,304
    const size_t SW1_L  = (size_t)NN * NN * 48;   // 12,582,912
    const size_t SB1_L  = (size_t)NN * NN * 3;
    const size_t SB2_L  = (size_t)NN * NN;
    const size_t AW1_L  = (size_t)NN * 3 * AGG_IN;
    const size_t AB1_L  = (size_t)NN * 3;
    const size_t AB2_L  = (size_t)NN;

    for (int l = 0; l < LTL; ++l) {
        const float* a_ext = (l == 0) ? x : nullptr;
        float* dw = (l == LTL - 1) ? out : nullptr;
        layer_kernel<<<NN, TPB>>>(
            a_ext, dw,
            /*in_buf=*/ (l == 1) ? 0 : 1,
            /*out_buf=*/(l == 0) ? 0 : 1,
            vec_W  + (size_t)l * VEC_L,  vec_b  + (size_t)l * VEC_L,
            syn_W1 + (size_t)l * SW1_L,  syn_b1 + (size_t)l * SB1_L,
            syn_W2 + (size_t)l * SB1_L,  syn_b2 + (size_t)l * SB2_L,
            agg_W1 + (size_t)l * AW1_L,  agg_b1 + (size_t)l * AB1_L,
            agg_W2 + (size_t)l * AB1_L,  agg_b2 + (size_t)l * AB2_L,
            l);
    }
}